// round 9
// baseline (speedup 1.0000x reference)
#include <cuda_runtime.h>
#include <cuda_fp16.h>
#include <cstdint>

// 3x3 s1 p1 conv, NCHW fp32 via mma.sync.m16n8k16 FP16 (f32 accumulate).
// R6 tile shape (warp = 16px x 16oc x 4 rows/phase, C=32 regs, LDS.32 A-gather,
// stride-72 conflict-free layout) + R7's resident input tile: all 18 input rows
// staged up front, ONE __syncthreads, then 4 barrier-free compute phases with
// linear slot addressing (no ring, no modulo -> lower reg pressure than R6).
// CTA = 64-px x-strip x 16 output rows x 1 image; 256 thr / 8 warps.
// Smem 101 KB -> 2 CTAs/SM. Direct sector-perfect STG.32 epilogue.

#define HW     256
#define ICN    32
#define OCN    32
#define SW     64            // strip width
#define XW     66            // strip + halo
#define YCH    16            // output rows per CTA
#define NROWS  18            // resident input rows
#define STRIDE 72            // u32 per kp row (==8 mod 32 -> conflict-free)
#define KPN    16            // ic/2 packed rows
#define SLOT_U (KPN * STRIDE)              // 1152 u32 = 4608 B
#define B_BYTES (9 * 2 * 4 * 32 * 8)       // 18432
#define SM_A    B_BYTES
#define SMEM_TOTAL (B_BYTES + NROWS * SLOT_U * 4)   // 101376 B

__device__ __forceinline__ uint32_t pack_h2(float a, float b) {
    uint32_t r;
    asm("cvt.rn.f16x2.f32 %0, %2, %1;" : "=r"(r) : "f"(a), "f"(b));
    return r;   // lo half = a, hi half = b
}

__device__ __forceinline__ void mma16(float c[4], uint32_t a0, uint32_t a1,
                                      uint32_t a2, uint32_t a3, uint2 b) {
    asm volatile(
        "mma.sync.aligned.m16n8k16.row.col.f32.f16.f16.f32 "
        "{%0,%1,%2,%3},{%4,%5,%6,%7},{%8,%9},{%0,%1,%2,%3};"
        : "+f"(c[0]), "+f"(c[1]), "+f"(c[2]), "+f"(c[3])
        : "r"(a0), "r"(a1), "r"(a2), "r"(a3), "r"(b.x), "r"(b.y));
}

// Stage input row yin into linear slot: half2-packed [ic/2][px], coalesced LDG.
__device__ __forceinline__ void build_row(const float* __restrict__ xn, int yin,
                                          int x0, uint32_t* __restrict__ slot,
                                          int tid) {
    bool yok = ((unsigned)yin < HW);
    const float* xr = xn + ((size_t)yin << 8);
    #pragma unroll
    for (int e = tid; e < KPN * XW; e += 256) {
        int kp = e / XW;
        int px = e - kp * XW;
        int gx = x0 - 1 + px;
        float v0 = 0.f, v1 = 0.f;
        if (yok && (unsigned)gx < HW) {
            const float* p = xr + (((size_t)kp * 2) << 16) + gx;
            v0 = p[0];
            v1 = p[1 << 16];
        }
        slot[kp * STRIDE + px] = pack_h2(v0, v1);
    }
}

__global__ __launch_bounds__(256, 2)
void conv3x3_f16_res_kernel(const float* __restrict__ xg,
                            const float* __restrict__ wg,
                            const float* __restrict__ bg,
                            float* __restrict__ out)
{
    extern __shared__ char smem[];
    uint32_t* smA = (uint32_t*)(smem + SM_A);
    const int tid  = threadIdx.x;
    const int warp = tid >> 5;
    const int lane = tid & 31;
    const int mt   = warp >> 1;     // m-tile 0..3
    const int nth  = warp & 1;      // n-tile half

    const int x0 = blockIdx.x * SW;
    const int y0 = blockIdx.y * YCH;
    const int n  = blockIdx.z;
    const float* xn = xg + (((size_t)n * ICN) << 16);

    // ---- Stage B (fragment order): 2304 uint2 frags, once per CTA
    #pragma unroll
    for (int it = 0; it < 9; it++) {
        int idx  = tid + it * 256;
        int l    = idx & 31;
        int nt   = (idx >> 5) & 3;
        int k0   = (idx >> 7) & 1;
        int tap  = idx >> 8;                    // dy*3+dx
        int oc   = nt * 8 + (l >> 2);
        int ic0  = k0 * 16 + (l & 3) * 2;
        const float* wp = wg + (size_t)oc * ICN * 9 + tap;
        uint2 w2;
        w2.x = pack_h2(wp[(size_t)ic0 * 9],       wp[(size_t)(ic0 + 1) * 9]);
        w2.y = pack_h2(wp[(size_t)(ic0 + 8) * 9], wp[(size_t)(ic0 + 9) * 9]);
        *(uint2*)(smem + ((((tap * 2 + k0) * 4 + nt) * 32 + l) << 3)) = w2;
    }

    // ---- Build ALL 18 input rows (y0-1 .. y0+16); one barrier total
    #pragma unroll 1
    for (int i = 0; i < NROWS; i++)
        build_row(xn, y0 - 1 + i, x0, smA + i * SLOT_U, tid);
    __syncthreads();

    const int t = lane & 3, g = lane >> 2;
    const uint2* bw = (const uint2*)smem + lane;
    const int gx = x0 + mt * 16 + g;
    const uint32_t lbase = t * STRIDE + mt * 16 + g;

    #pragma unroll 1
    for (int p = 0; p < YCH / 4; p++) {
        const int y = y0 + 4 * p;           // rows y .. y+3 (no syncs between phases)

        float c[4][2][4];
        #pragma unroll
        for (int r = 0; r < 4; r++)
            #pragma unroll
            for (int j = 0; j < 2; j++)
                #pragma unroll
                for (int i = 0; i < 4; i++) c[r][j][i] = 0.f;

        #pragma unroll
        for (int k0 = 0; k0 < 2; k0++) {
            #pragma unroll
            for (int dx = 0; dx < 3; dx++) {
                // cache 6 B frags (3 dy x 2 nt) in regs
                uint2 b[3][2];
                #pragma unroll
                for (int dy = 0; dy < 3; dy++)
                    #pragma unroll
                    for (int j = 0; j < 2; j++)
                        b[dy][j] = bw[(size_t)((((dy * 3 + dx) * 2 + k0) * 4
                                                + nth * 2 + j)) * 32];

                // slots 4p .. 4p+5 = input rows y-1 .. y+4, linear walk
                const uint32_t* s = smA + (4 * p) * SLOT_U + lbase
                                        + k0 * 8 * STRIDE + dx;
                #pragma unroll
                for (int i = 0; i < 6; i++) {
                    uint32_t a0 = s[0], a1 = s[8];
                    uint32_t a2 = s[4 * STRIDE], a3 = s[4 * STRIDE + 8];
                    #pragma unroll
                    for (int dy = 0; dy < 3; dy++) {
                        int rl = i - dy;
                        if (rl >= 0 && rl < 4) {
                            mma16(c[rl][0], a0, a1, a2, a3, b[dy][0]);
                            mma16(c[rl][1], a0, a1, a2, a3, b[dy][1]);
                        }
                    }
                    s += SLOT_U;
                }
            }
        }

        // ---- Epilogue: direct stores (sector-perfect STG.32)
        #pragma unroll
        for (int j = 0; j < 2; j++) {
            int oc0 = (nth * 2 + j) * 8 + 2 * t;
            float b0 = bg[oc0], b1 = bg[oc0 + 1];
            #pragma unroll
            for (int rl = 0; rl < 4; rl++) {
                float* o = out + (((size_t)(n * OCN + oc0)) << 16)
                               + ((size_t)(y + rl) << 8) + gx;
                o[0]                     = c[rl][j][0] + b0;
                o[(size_t)1 << 16]       = c[rl][j][1] + b1;
                o[8]                     = c[rl][j][2] + b0;
                o[((size_t)1 << 16) + 8] = c[rl][j][3] + b1;
            }
        }
    }
}

extern "C" void kernel_launch(void* const* d_in, const int* in_sizes, int n_in,
                              void* d_out, int out_size) {
    const float* x = (const float*)d_in[0];
    const float* w = (const float*)d_in[1];
    const float* b = (const float*)d_in[2];
    float* out = (float*)d_out;

    cudaFuncSetAttribute(conv3x3_f16_res_kernel,
                         cudaFuncAttributeMaxDynamicSharedMemorySize, SMEM_TOTAL);

    dim3 grid(HW / SW, HW / YCH, 16);   // (4, 16, 16) = 1024 CTAs
    conv3x3_f16_res_kernel<<<grid, 256, SMEM_TOTAL>>>(x, w, b, out);
}

// round 10
// speedup vs baseline: 1.4425x; 1.4425x over previous
#include <cuda_runtime.h>
#include <cuda_fp16.h>
#include <cstdint>

// 3x3 s1 p1 conv, NCHW fp32 via mma.sync.m16n8k16 FP16 (f32 accumulate).
// == R6 kernel (106.6 us: 4-row warp phases, ring-of-6 input rows, interleaved
// build/compute with 2 syncs per phase) with __launch_bounds__(256,3):
// R9 proved the compute body fits in 83 regs, so forcing <=84 regs lifts
// occupancy to 3 CTAs/SM (24 warps, 6/SMSP) for ~1.5x issue-slot headroom.
// CTA = 64-px x-strip x 16 output rows x 1 image; 256 thr / 8 warps.
// Warp = 1 m-tile (16 px) x 2 n-tiles (16 oc) x 4 rows per phase (C=32 regs).
// A: half2-packed [ic/2][px], stride 72 (conflict-free). Smem 46 KB.
// Direct sector-perfect STG.32 epilogue.

#define HW     256
#define ICN    32
#define OCN    32
#define SW     64            // strip width
#define XW     66            // strip + halo
#define YCH    16            // output rows per CTA
#define STRIDE 72            // u32 per kp row (==8 mod 32 -> conflict-free)
#define KPN    16            // ic/2 packed rows
#define SLOT_U (KPN * STRIDE)              // 1152 u32 = 4608 B
#define B_BYTES (9 * 2 * 4 * 32 * 8)       // 18432
#define SM_A    B_BYTES
#define NSLOT   6
#define SMEM_TOTAL (B_BYTES + NSLOT * SLOT_U * 4)   // 46080 B

__device__ __forceinline__ uint32_t pack_h2(float a, float b) {
    uint32_t r;
    asm("cvt.rn.f16x2.f32 %0, %2, %1;" : "=r"(r) : "f"(a), "f"(b));
    return r;   // lo half = a, hi half = b
}

__device__ __forceinline__ void mma16(float c[4], uint32_t a0, uint32_t a1,
                                      uint32_t a2, uint32_t a3, uint2 b) {
    asm volatile(
        "mma.sync.aligned.m16n8k16.row.col.f32.f16.f16.f32 "
        "{%0,%1,%2,%3},{%4,%5,%6,%7},{%8,%9},{%0,%1,%2,%3};"
        : "+f"(c[0]), "+f"(c[1]), "+f"(c[2]), "+f"(c[3])
        : "r"(a0), "r"(a1), "r"(a2), "r"(a3), "r"(b.x), "r"(b.y));
}

// Stage input row yin into ring slot (yin mod 6): half2-packed [ic/2][px].
__device__ __forceinline__ void build_row(const float* __restrict__ xn, int yin,
                                          int x0, uint32_t* __restrict__ smA,
                                          int tid) {
    uint32_t* slot = smA + ((yin + 2 * NSLOT) % NSLOT) * SLOT_U;
    bool yok = ((unsigned)yin < HW);
    const float* xr = xn + ((size_t)yin << 8);
    #pragma unroll
    for (int e = tid; e < KPN * XW; e += 256) {
        int kp = e / XW;
        int px = e - kp * XW;
        int gx = x0 - 1 + px;
        float v0 = 0.f, v1 = 0.f;
        if (yok && (unsigned)gx < HW) {
            const float* p = xr + (((size_t)kp * 2) << 16) + gx;
            v0 = p[0];
            v1 = p[1 << 16];
        }
        slot[kp * STRIDE + px] = pack_h2(v0, v1);
    }
}

__global__ __launch_bounds__(256, 3)
void conv3x3_f16_occ3_kernel(const float* __restrict__ xg,
                             const float* __restrict__ wg,
                             const float* __restrict__ bg,
                             float* __restrict__ out)
{
    extern __shared__ char smem[];
    uint32_t* smA = (uint32_t*)(smem + SM_A);
    const int tid  = threadIdx.x;
    const int warp = tid >> 5;
    const int lane = tid & 31;
    const int mt   = warp >> 1;     // m-tile 0..3
    const int nth  = warp & 1;      // n-tile half

    const int x0 = blockIdx.x * SW;
    const int y0 = blockIdx.y * YCH;
    const int n  = blockIdx.z;
    const float* xn = xg + (((size_t)n * ICN) << 16);

    // ---- Stage B (fragment order): 2304 uint2 frags, once per CTA
    #pragma unroll
    for (int it = 0; it < 9; it++) {
        int idx  = tid + it * 256;
        int l    = idx & 31;
        int nt   = (idx >> 5) & 3;
        int k0   = (idx >> 7) & 1;
        int tap  = idx >> 8;                    // dy*3+dx
        int oc   = nt * 8 + (l >> 2);
        int ic0  = k0 * 16 + (l & 3) * 2;
        const float* wp = wg + (size_t)oc * ICN * 9 + tap;
        uint2 w2;
        w2.x = pack_h2(wp[(size_t)ic0 * 9],       wp[(size_t)(ic0 + 1) * 9]);
        w2.y = pack_h2(wp[(size_t)(ic0 + 8) * 9], wp[(size_t)(ic0 + 9) * 9]);
        *(uint2*)(smem + ((((tap * 2 + k0) * 4 + nt) * 32 + l) << 3)) = w2;
    }

    // ---- Prologue rows
    build_row(xn, y0 - 1, x0, smA, tid);
    build_row(xn, y0,     x0, smA, tid);

    const int t = lane & 3, g = lane >> 2;
    const uint2* bw = (const uint2*)smem + lane;
    const int gx = x0 + mt * 16 + g;
    const uint32_t lbase = t * STRIDE + mt * 16 + g;

    #pragma unroll 1
    for (int p = 0; p < YCH / 4; p++) {
        const int y = y0 + 4 * p;           // rows y .. y+3

        __syncthreads();                    // prev phase's LDS reads done
        build_row(xn, y + 1, x0, smA, tid);
        build_row(xn, y + 2, x0, smA, tid);
        build_row(xn, y + 3, x0, smA, tid);
        build_row(xn, y + 4, x0, smA, tid);
        __syncthreads();                    // slots y-1 .. y+4 ready

        float c[4][2][4];
        #pragma unroll
        for (int r = 0; r < 4; r++)
            #pragma unroll
            for (int j = 0; j < 2; j++)
                #pragma unroll
                for (int i = 0; i < 4; i++) c[r][j][i] = 0.f;

        uint32_t so[NSLOT];
        #pragma unroll
        for (int i = 0; i < NSLOT; i++)
            so[i] = ((y - 1 + i + 2 * NSLOT) % NSLOT) * SLOT_U + lbase;

        #pragma unroll
        for (int k0 = 0; k0 < 2; k0++) {
            #pragma unroll
            for (int dx = 0; dx < 3; dx++) {
                // cache 6 B frags (3 dy x 2 nt) in regs
                uint2 b[3][2];
                #pragma unroll
                for (int dy = 0; dy < 3; dy++)
                    #pragma unroll
                    for (int j = 0; j < 2; j++)
                        b[dy][j] = bw[(size_t)((((dy * 3 + dx) * 2 + k0) * 4
                                                + nth * 2 + j)) * 32];

                const int ao = k0 * 8 * STRIDE + dx;

                #pragma unroll
                for (int i = 0; i < NSLOT; i++) {
                    const uint32_t* s = smA + so[i] + ao;
                    uint32_t a0 = s[0], a1 = s[8];
                    uint32_t a2 = s[4 * STRIDE], a3 = s[4 * STRIDE + 8];
                    #pragma unroll
                    for (int dy = 0; dy < 3; dy++) {
                        int rl = i - dy;
                        if (rl >= 0 && rl < 4) {
                            mma16(c[rl][0], a0, a1, a2, a3, b[dy][0]);
                            mma16(c[rl][1], a0, a1, a2, a3, b[dy][1]);
                        }
                    }
                }
            }
        }

        // ---- Epilogue: direct stores (sector-perfect STG.32)
        #pragma unroll
        for (int j = 0; j < 2; j++) {
            int oc0 = (nth * 2 + j) * 8 + 2 * t;
            float b0 = bg[oc0], b1 = bg[oc0 + 1];
            #pragma unroll
            for (int rl = 0; rl < 4; rl++) {
                float* o = out + (((size_t)(n * OCN + oc0)) << 16)
                               + ((size_t)(y + rl) << 8) + gx;
                o[0]                     = c[rl][j][0] + b0;
                o[(size_t)1 << 16]       = c[rl][j][1] + b1;
                o[8]                     = c[rl][j][2] + b0;
                o[((size_t)1 << 16) + 8] = c[rl][j][3] + b1;
            }
        }
    }
}

extern "C" void kernel_launch(void* const* d_in, const int* in_sizes, int n_in,
                              void* d_out, int out_size) {
    const float* x = (const float*)d_in[0];
    const float* w = (const float*)d_in[1];
    const float* b = (const float*)d_in[2];
    float* out = (float*)d_out;

    cudaFuncSetAttribute(conv3x3_f16_occ3_kernel,
                         cudaFuncAttributeMaxDynamicSharedMemorySize, SMEM_TOTAL);

    dim3 grid(HW / SW, HW / YCH, 16);   // (4, 16, 16) = 1024 CTAs
    conv3x3_f16_occ3_kernel<<<grid, 256, SMEM_TOTAL>>>(x, w, b, out);
}